// round 8
// baseline (speedup 1.0000x reference)
#include <cuda_runtime.h>

#define BATCH 4
#define DD 160
#define HH 192
#define WW 160
#define HW (HH * WW)                 // 30720
#define VOX (DD * HH * WW)           // 4,915,200

#define TD 8
#define TH 8
#define TW 40
#define TPB 256
#define VPT ((TD * TH * TW) / TPB)   // 10 voxels per thread
#define CAPW 10240                   // smem window capacity (floats) = 40KB

__global__ __launch_bounds__(TPB) void st_affine_trilinear_v8(
    const float* __restrict__ vol,   // [B, D, H, W]
    const float* __restrict__ trf,   // [B, 4, 4]
    float* __restrict__ out)         // [B, D, H, W]
{
    __shared__ float sm[CAPW];

    const int bi = blockIdx.x;
    const int wb = bi & 3;
    const int t1 = bi >> 2;
    const int hb = t1 % 24;
    const int t2 = t1 / 24;
    const int db = t2 % 20;
    const int b  = t2 / 20;

    const int bd = db * TD, bh = hb * TH, bw = wb * TW;

    const float* A = trf + b * 16;
    const float a00 = A[0], a01 = A[1], a02 = A[2],  a03 = A[3];
    const float a10 = A[4], a11 = A[5], a12 = A[6],  a13 = A[7];
    const float a20 = A[8], a21 = A[9], a22 = A[10], a23 = A[11];

    const float cD = (DD - 1) * 0.5f, cH = (HH - 1) * 0.5f, cW = (WW - 1) * 0.5f;
    const float mD = (float)(DD - 1), mH = (float)(HH - 1), mW = (float)(WW - 1);
    const float* v = vol + b * VOX;

    // ---- exact per-block input window from the 8 tile corners (affine) ----
    const float p0 = (float)bd - cD,        p1 = (float)(bd + TD - 1) - cD;
    const float q0 = (float)bh - cH,        q1 = (float)(bh + TH - 1) - cH;
    const float r0 = (float)bw - cW,        r1 = (float)(bw + TW - 1) - cW;

    #define RANGE(a, bb, c, t, lo, hi)                                        \
        {  const float _t = (t);                                              \
           lo = _t + fminf(a * p0, a * p1) + fminf(bb * q0, bb * q1)          \
                   + fminf(c * r0, c * r1);                                   \
           hi = _t + fmaxf(a * p0, a * p1) + fmaxf(bb * q0, bb * q1)          \
                   + fmaxf(c * r0, c * r1); }

    float lod, hid, loh, hih, low, hiw;
    RANGE(a00, a01, a02, a03 + cD, lod, hid);
    RANGE(a10, a11, a12, a13 + cH, loh, hih);
    RANGE(a20, a21, a22, a23 + cW, low, hiw);

    const int ild = (int)fminf(floorf(fminf(fmaxf(lod, 0.f), mD)), mD - 1.f);
    const int ihd = (int)fminf(floorf(fminf(fmaxf(hid, 0.f), mD)), mD - 1.f) + 1;
    const int ilh = (int)fminf(floorf(fminf(fmaxf(loh, 0.f), mH)), mH - 1.f);
    const int ihh = (int)fminf(floorf(fminf(fmaxf(hih, 0.f), mH)), mH - 1.f) + 1;
    const int ilw = (int)fminf(floorf(fminf(fmaxf(low, 0.f), mW)), mW - 1.f);
    const int ihw = (int)fminf(floorf(fminf(fmaxf(hiw, 0.f), mW)), mW - 1.f) + 1;

    const int wdn = ihd - ild + 1;     // window rows: [ild .. ihd] inclusive
    const int whn = ihh - ilh + 1;
    const int wwn = ihw - ilw + 1;
    const int pitch = wwn | 1;          // odd pitch: decorrelate bank strides
    const int sp = whn * pitch;

    const int tid  = threadIdx.x;
    const int wy   = tid >> 5;
    const int lane = tid & 31;

    const float ildf = (float)ild, ilhf = (float)ilh, ilwf = (float)ilw;
    // Max legal i0 per axis (i0+1 still inside the window):
    const float fdm = (float)(ihd - 1), fhm = (float)(ihh - 1), fwm = (float)(ihw - 1);

    if (wdn * sp <= CAPW) {
        // ---- cooperative window fill (coalesced) ----
        for (int z = 0; z < wdn; ++z) {
            const float* src = v + (ild + z) * HW + ilw;
            float* dst = sm + z * sp;
            for (int y = wy; y < whn; y += 8)
                for (int x = lane; x < wwn; x += 32)
                    dst[y * pitch + x] = __ldg(src + (ilh + y) * WW + x);
        }
        __syncthreads();

        // ---- per-voxel gather from smem ----
        #pragma unroll
        for (int k = 0; k < VPT; k++) {
            const int vv = tid + k * TPB;
            const int dz = vv / (TH * TW);
            const int rr = vv - dz * (TH * TW);
            const int hy = rr / TW;
            const int wx = rr - hy * TW;

            const float pd = (float)(bd + dz) - cD;
            const float ph = (float)(bh + hy) - cH;
            const float pw = (float)(bw + wx) - cW;

            const float ld = fmaf(a00, pd, fmaf(a01, ph, fmaf(a02, pw, a03))) + cD;
            const float lh = fmaf(a10, pd, fmaf(a11, ph, fmaf(a12, pw, a13))) + cH;
            const float lw = fmaf(a20, pd, fmaf(a21, ph, fmaf(a22, pw, a23))) + cW;

            const float td = fminf(fmaxf(ld, 0.0f), mD);
            const float th = fminf(fmaxf(lh, 0.0f), mH);
            const float tw = fminf(fmaxf(lw, 0.0f), mW);

            // clamp floor into window: max i0 = ih*-1 (FIXED off-by-one)
            const float f0d = fminf(fmaxf(floorf(td), ildf), fdm);
            const float f0h = fminf(fmaxf(floorf(th), ilhf), fhm);
            const float f0w = fminf(fmaxf(floorf(tw), ilwf), fwm);

            const float w0d = (f0d - td) + 1.0f;
            const float w0h = (f0h - th) + 1.0f;
            const float w0w = (f0w - tw) + 1.0f;

            const int zd = (int)f0d - ild;
            const int yh = (int)f0h - ilh;
            const int xw = (int)f0w - ilw;

            const int a0 = (zd * whn + yh) * pitch + xw;   // (d0,h0)
            const int a1 = a0 + pitch;                     // (d0,h1)
            const int a2 = a0 + sp;                        // (d1,h0)
            const int a3 = a2 + pitch;                     // (d1,h1)

            const float v000 = sm[a0],     v001 = sm[a0 + 1];
            const float v010 = sm[a1],     v011 = sm[a1 + 1];
            const float v100 = sm[a2],     v101 = sm[a2 + 1];
            const float v110 = sm[a3],     v111 = sm[a3 + 1];

            const float e00 = fmaf(w0w, v000 - v001, v001);
            const float e01 = fmaf(w0w, v010 - v011, v011);
            const float e10 = fmaf(w0w, v100 - v101, v101);
            const float e11 = fmaf(w0w, v110 - v111, v111);
            const float e0  = fmaf(w0h, e00 - e01, e01);
            const float e1  = fmaf(w0h, e10 - e11, e11);

            out[b * VOX + (bd + dz) * HW + (bh + hy) * WW + bw + wx] =
                fmaf(w0d, e0 - e1, e1);
        }
    } else {
        // ---- uniform fallback: direct global gather (v3 semantics) ----
        #pragma unroll
        for (int k = 0; k < VPT; k++) {
            const int vv = tid + k * TPB;
            const int dz = vv / (TH * TW);
            const int rr = vv - dz * (TH * TW);
            const int hy = rr / TW;
            const int wx = rr - hy * TW;

            const float pd = (float)(bd + dz) - cD;
            const float ph = (float)(bh + hy) - cH;
            const float pw = (float)(bw + wx) - cW;

            const float ld = fmaf(a00, pd, fmaf(a01, ph, fmaf(a02, pw, a03))) + cD;
            const float lh = fmaf(a10, pd, fmaf(a11, ph, fmaf(a12, pw, a13))) + cH;
            const float lw = fmaf(a20, pd, fmaf(a21, ph, fmaf(a22, pw, a23))) + cW;

            const float td = fminf(fmaxf(ld, 0.0f), mD);
            const float th = fminf(fmaxf(lh, 0.0f), mH);
            const float tw = fminf(fmaxf(lw, 0.0f), mW);

            const float f0d = fminf(floorf(td), mD - 1.0f);
            const float f0h = fminf(floorf(th), mH - 1.0f);
            const float f0w = fminf(floorf(tw), mW - 1.0f);

            const float w0d = (f0d - td) + 1.0f;
            const float w0h = (f0h - th) + 1.0f;
            const float w0w = (f0w - tw) + 1.0f;

            const int c00 = (int)f0d * HW + (int)f0h * WW + (int)f0w;
            const int c01 = c00 + WW;
            const int c10 = c00 + HW;
            const int c11 = c10 + WW;

            const float v000 = __ldg(v + c00), v001 = __ldg(v + c00 + 1);
            const float v010 = __ldg(v + c01), v011 = __ldg(v + c01 + 1);
            const float v100 = __ldg(v + c10), v101 = __ldg(v + c10 + 1);
            const float v110 = __ldg(v + c11), v111 = __ldg(v + c11 + 1);

            const float e00 = fmaf(w0w, v000 - v001, v001);
            const float e01 = fmaf(w0w, v010 - v011, v011);
            const float e10 = fmaf(w0w, v100 - v101, v101);
            const float e11 = fmaf(w0w, v110 - v111, v111);
            const float e0  = fmaf(w0h, e00 - e01, e01);
            const float e1  = fmaf(w0h, e10 - e11, e11);

            out[b * VOX + (bd + dz) * HW + (bh + hy) * WW + bw + wx] =
                fmaf(w0d, e0 - e1, e1);
        }
    }
}

extern "C" void kernel_launch(void* const* d_in, const int* in_sizes, int n_in,
                              void* d_out, int out_size) {
    const float* vol = (const float*)d_in[0];
    const float* trf = (const float*)d_in[1];
    float* out = (float*)d_out;
    const int blocks = BATCH * (DD / TD) * (HH / TH) * (WW / TW);   // 7680
    st_affine_trilinear_v8<<<blocks, TPB>>>(vol, trf, out);
}

// round 9
// speedup vs baseline: 1.0667x; 1.0667x over previous
#include <cuda_runtime.h>

#define BATCH 4
#define DD 160
#define HH 192
#define WW 160
#define HW (HH * WW)                 // 30720
#define VOX (DD * HH * WW)           // 4,915,200

#define TD 8
#define TH 8
#define TW 32                        // TH*TW = 256 = TPB
#define TPB 256
#define VPT TD                       // one d-layer per k

// Static smem window layout (compile-time strides)
#define WDS 16
#define WHS 16
#define WPS 44
#define SZ  (WHS * WPS)              // 704, d-layer stride
#define SMS (WDS * SZ)               // 11264 floats = 44KB

__global__ __launch_bounds__(TPB) void st_affine_trilinear_v9(
    const float* __restrict__ vol,   // [B, D, H, W]
    const float* __restrict__ trf,   // [B, 4, 4]
    float* __restrict__ out)         // [B, D, H, W]
{
    __shared__ float sm[SMS];

    // block -> (b, db, hb, wb); 5 w-tiles, 24 h-tiles, 20 d-tiles, 4 batches
    const int bi = blockIdx.x;
    const int wb = bi % 5;
    const int t1 = bi / 5;
    const int hb = t1 % 24;
    const int t2 = t1 / 24;
    const int db = t2 % 20;
    const int b  = t2 / 20;

    const int bd = db * TD, bh = hb * TH, bw = wb * TW;

    const float* A = trf + b * 16;
    const float a00 = A[0], a01 = A[1], a02 = A[2],  a03 = A[3];
    const float a10 = A[4], a11 = A[5], a12 = A[6],  a13 = A[7];
    const float a20 = A[8], a21 = A[9], a22 = A[10], a23 = A[11];

    const float cD = (DD - 1) * 0.5f, cH = (HH - 1) * 0.5f, cW = (WW - 1) * 0.5f;
    const float mD = (float)(DD - 1), mH = (float)(HH - 1), mW = (float)(WW - 1);
    const float* v = vol + b * VOX;

    // ---- window bounds: evaluate the EXACT per-voxel formula at 8 corners ----
    float lodv =  1e30f, hidv = -1e30f;
    float lohv =  1e30f, hihv = -1e30f;
    float lowv =  1e30f, hiwv = -1e30f;
    #pragma unroll
    for (int c = 0; c < 8; c++) {
        const float pd = (float)(bd + ((c & 4) ? TD - 1 : 0)) - cD;
        const float ph = (float)(bh + ((c & 2) ? TH - 1 : 0)) - cH;
        const float pw = (float)(bw + ((c & 1) ? TW - 1 : 0)) - cW;
        const float ld = fmaf(a00, pd, fmaf(a01, ph, fmaf(a02, pw, a03))) + cD;
        const float lh = fmaf(a10, pd, fmaf(a11, ph, fmaf(a12, pw, a13))) + cH;
        const float lw = fmaf(a20, pd, fmaf(a21, ph, fmaf(a22, pw, a23))) + cW;
        lodv = fminf(lodv, ld); hidv = fmaxf(hidv, ld);
        lohv = fminf(lohv, lh); hihv = fmaxf(hihv, lh);
        lowv = fminf(lowv, lw); hiwv = fmaxf(hiwv, lw);
    }

    const int ild = (int)fminf(floorf(fminf(fmaxf(lodv, 0.f), mD)), mD - 1.f);
    const int ihd = (int)fminf(floorf(fminf(fmaxf(hidv, 0.f), mD)), mD - 1.f) + 1;
    const int ilh = (int)fminf(floorf(fminf(fmaxf(lohv, 0.f), mH)), mH - 1.f);
    const int ihh = (int)fminf(floorf(fminf(fmaxf(hihv, 0.f), mH)), mH - 1.f) + 1;
    const int ilw = (int)fminf(floorf(fminf(fmaxf(lowv, 0.f), mW)), mW - 1.f);
    const int ihw = (int)fminf(floorf(fminf(fmaxf(hiwv, 0.f), mW)), mW - 1.f) + 1;

    const int wdn = ihd - ild + 1;   // layers [ild..ihd]
    const int whn = ihh - ilh + 1;
    const int wwn = ihw - ilw + 1;

    const int tid  = threadIdx.x;
    const int lane = tid & 31;
    const int wid  = tid >> 5;

    // per-thread output coords (fixed; k walks d)
    const int wx = tid & 31;           // 0..31
    const int hy = (tid >> 5) & 7;     // 0..7

    const float ph  = (float)(bh + hy) - cH;
    const float pw  = (float)(bw + wx) - cW;
    const float pd0 = (float)bd - cD;

    // hoisted inner fma (identical fp order to reference chain)
    const float t1d = fmaf(a01, ph, fmaf(a02, pw, a03));
    const float t1h = fmaf(a11, ph, fmaf(a12, pw, a13));
    const float t1w = fmaf(a21, ph, fmaf(a22, pw, a23));

    if (wdn <= WDS && whn <= WHS && wwn <= WPS) {
        // ---- cooperative fill: rows (z,y), subtract-loop decode, static dst strides ----
        {
            const int nrows = wdn * whn;
            int rr = wid;            // 8 warps stride rows
            int z = 0;
            while (rr >= whn) { rr -= whn; z++; }
            for (int rowi = wid; rowi < nrows; rowi += 8) {
                const float* src = v + (ild + z) * HW + (ilh + rr) * WW + ilw;
                float* dst = sm + z * SZ + rr * WPS;
                for (int x = lane; x < wwn; x += 32)
                    dst[x] = __ldg(src + x);
                rr += 8;
                while (rr >= whn) { rr -= whn; z++; }
            }
        }
        __syncthreads();

        const float ildf = (float)ild, ilhf = (float)ilh, ilwf = (float)ilw;
        const float fdm = (float)(ihd - 1), fhm = (float)(ihh - 1), fwm = (float)(ihw - 1);

        int oidx = b * VOX + bd * HW + (bh + hy) * WW + bw + wx;

        #pragma unroll
        for (int k = 0; k < VPT; k++) {
            const float pd = pd0 + (float)k;
            const float ld = fmaf(a00, pd, t1d) + cD;
            const float lh = fmaf(a10, pd, t1h) + cH;
            const float lw = fmaf(a20, pd, t1w) + cW;

            const float td = fminf(fmaxf(ld, 0.0f), mD);
            const float th = fminf(fmaxf(lh, 0.0f), mH);
            const float tw = fminf(fmaxf(lw, 0.0f), mW);

            const float f0d = fminf(fmaxf(floorf(td), ildf), fdm);
            const float f0h = fminf(fmaxf(floorf(th), ilhf), fhm);
            const float f0w = fminf(fmaxf(floorf(tw), ilwf), fwm);

            const float w0d = (f0d - td) + 1.0f;
            const float w0h = (f0h - th) + 1.0f;
            const float w0w = (f0w - tw) + 1.0f;

            const int zd = (int)f0d - ild;
            const int yh = (int)f0h - ilh;
            const int xw = (int)f0w - ilw;

            const int a0 = zd * SZ + yh * WPS + xw;   // (d0,h0) — static strides
            const int a1 = a0 + WPS;                  // (d0,h1)
            const int a2 = a0 + SZ;                   // (d1,h0)
            const int a3 = a2 + WPS;                  // (d1,h1)

            const float v000 = sm[a0],     v001 = sm[a0 + 1];
            const float v010 = sm[a1],     v011 = sm[a1 + 1];
            const float v100 = sm[a2],     v101 = sm[a2 + 1];
            const float v110 = sm[a3],     v111 = sm[a3 + 1];

            const float e00 = fmaf(w0w, v000 - v001, v001);
            const float e01 = fmaf(w0w, v010 - v011, v011);
            const float e10 = fmaf(w0w, v100 - v101, v101);
            const float e11 = fmaf(w0w, v110 - v111, v111);
            const float e0  = fmaf(w0h, e00 - e01, e01);
            const float e1  = fmaf(w0h, e10 - e11, e11);

            out[oidx] = fmaf(w0d, e0 - e1, e1);
            oidx += HW;
        }
    } else {
        // ---- uniform fallback: direct global gather (reference semantics) ----
        int oidx = b * VOX + bd * HW + (bh + hy) * WW + bw + wx;
        #pragma unroll
        for (int k = 0; k < VPT; k++) {
            const float pd = pd0 + (float)k;
            const float ld = fmaf(a00, pd, t1d) + cD;
            const float lh = fmaf(a10, pd, t1h) + cH;
            const float lw = fmaf(a20, pd, t1w) + cW;

            const float td = fminf(fmaxf(ld, 0.0f), mD);
            const float th = fminf(fmaxf(lh, 0.0f), mH);
            const float tw = fminf(fmaxf(lw, 0.0f), mW);

            const float f0d = fminf(floorf(td), mD - 1.0f);
            const float f0h = fminf(floorf(th), mH - 1.0f);
            const float f0w = fminf(floorf(tw), mW - 1.0f);

            const float w0d = (f0d - td) + 1.0f;
            const float w0h = (f0h - th) + 1.0f;
            const float w0w = (f0w - tw) + 1.0f;

            const int c00 = (int)f0d * HW + (int)f0h * WW + (int)f0w;
            const int c01 = c00 + WW;
            const int c10 = c00 + HW;
            const int c11 = c10 + WW;

            const float v000 = __ldg(v + c00), v001 = __ldg(v + c00 + 1);
            const float v010 = __ldg(v + c01), v011 = __ldg(v + c01 + 1);
            const float v100 = __ldg(v + c10), v101 = __ldg(v + c10 + 1);
            const float v110 = __ldg(v + c11), v111 = __ldg(v + c11 + 1);

            const float e00 = fmaf(w0w, v000 - v001, v001);
            const float e01 = fmaf(w0w, v010 - v011, v011);
            const float e10 = fmaf(w0w, v100 - v101, v101);
            const float e11 = fmaf(w0w, v110 - v111, v111);
            const float e0  = fmaf(w0h, e00 - e01, e01);
            const float e1  = fmaf(w0h, e10 - e11, e11);

            out[oidx] = fmaf(w0d, e0 - e1, e1);
            oidx += HW;
        }
    }
}

extern "C" void kernel_launch(void* const* d_in, const int* in_sizes, int n_in,
                              void* d_out, int out_size) {
    const float* vol = (const float*)d_in[0];
    const float* trf = (const float*)d_in[1];
    float* out = (float*)d_out;
    const int blocks = BATCH * (DD / TD) * (HH / TH) * (WW / TW);   // 9600
    st_affine_trilinear_v9<<<blocks, TPB>>>(vol, trf, out);
}

// round 10
// speedup vs baseline: 2.0754x; 1.9457x over previous
#include <cuda_runtime.h>

#define BATCH 4
#define DD 160
#define HH 192
#define WW 160
#define HW (HH * WW)                 // 30720
#define VOX (DD * HH * WW)           // 4,915,200

#define TD 8
#define TH 8
#define TW 32                        // TH*TW = 256 = TPB
#define TPB 256
#define VPT TD

// Static smem window: 14 d-layers x 14 h-rows x 48 w (16B-aligned pitch)
#define WDS 14
#define WHS 14
#define WPS 48
#define SZ  (WHS * WPS)              // 672
#define SMS (WDS * SZ)               // 9408 floats = 37.6KB

__global__ __launch_bounds__(TPB) void st_affine_trilinear_v10(
    const float* __restrict__ vol,   // [B, D, H, W]
    const float* __restrict__ trf,   // [B, 4, 4]
    float* __restrict__ out)         // [B, D, H, W]
{
    __shared__ float sm[SMS];

    const int bi = blockIdx.x;
    const int wb = bi % 5;
    const int t1 = bi / 5;
    const int hb = t1 % 24;
    const int t2 = t1 / 24;
    const int db = t2 % 20;
    const int b  = t2 / 20;

    const int bd = db * TD, bh = hb * TH, bw = wb * TW;

    const float* A = trf + b * 16;
    const float a00 = A[0], a01 = A[1], a02 = A[2],  a03 = A[3];
    const float a10 = A[4], a11 = A[5], a12 = A[6],  a13 = A[7];
    const float a20 = A[8], a21 = A[9], a22 = A[10], a23 = A[11];

    const float cD = (DD - 1) * 0.5f, cH = (HH - 1) * 0.5f, cW = (WW - 1) * 0.5f;
    const float mD = (float)(DD - 1), mH = (float)(HH - 1), mW = (float)(WW - 1);
    const float* v = vol + b * VOX;

    // ---- window bounds: exact per-voxel fma chain evaluated at 8 tile corners ----
    float lodv =  1e30f, hidv = -1e30f;
    float lohv =  1e30f, hihv = -1e30f;
    float lowv =  1e30f, hiwv = -1e30f;
    #pragma unroll
    for (int c = 0; c < 8; c++) {
        const float pd = (float)(bd + ((c & 4) ? TD - 1 : 0)) - cD;
        const float ph = (float)(bh + ((c & 2) ? TH - 1 : 0)) - cH;
        const float pw = (float)(bw + ((c & 1) ? TW - 1 : 0)) - cW;
        const float ld = fmaf(a00, pd, fmaf(a01, ph, fmaf(a02, pw, a03))) + cD;
        const float lh = fmaf(a10, pd, fmaf(a11, ph, fmaf(a12, pw, a13))) + cH;
        const float lw = fmaf(a20, pd, fmaf(a21, ph, fmaf(a22, pw, a23))) + cW;
        lodv = fminf(lodv, ld); hidv = fmaxf(hidv, ld);
        lohv = fminf(lohv, lh); hihv = fmaxf(hihv, lh);
        lowv = fminf(lowv, lw); hiwv = fmaxf(hiwv, lw);
    }

    const int ild = (int)fminf(floorf(fminf(fmaxf(lodv, 0.f), mD)), mD - 1.f);
    const int ihd = (int)fminf(floorf(fminf(fmaxf(hidv, 0.f), mD)), mD - 1.f) + 1;
    const int ilh = (int)fminf(floorf(fminf(fmaxf(lohv, 0.f), mH)), mH - 1.f);
    const int ihh = (int)fminf(floorf(fminf(fmaxf(hihv, 0.f), mH)), mH - 1.f) + 1;
    const int ilw = (int)fminf(floorf(fminf(fmaxf(lowv, 0.f), mW)), mW - 1.f);
    const int ihw = (int)fminf(floorf(fminf(fmaxf(hiwv, 0.f), mW)), mW - 1.f) + 1;

    const int ilw_al = ilw & ~3;       // 16B-aligned window start in w
    const int wdn = ihd - ild + 1;
    const int whn = ihh - ilh + 1;
    const int wal = ihw - ilw_al + 1;  // aligned w-extent

    const int tid = threadIdx.x;
    const int wx  = tid & 31;
    const int hy  = (tid >> 5) & 7;

    const float ph  = (float)(bh + hy) - cH;
    const float pw  = (float)(bw + wx) - cW;
    const float pd0 = (float)bd - cD;

    const float t1d = fmaf(a01, ph, fmaf(a02, pw, a03));
    const float t1h = fmaf(a11, ph, fmaf(a12, pw, a13));
    const float t1w = fmaf(a21, ph, fmaf(a22, pw, a23));

    if (wdn <= WDS && whn <= WHS && wal <= WPS) {
        // ---- flat float4 job fill ----
        {
            const int nj = wdn * whn * 12;                       // 12 float4 per row
            const unsigned mwhn = (0x100000u + (unsigned)whn - 1u) / (unsigned)whn;
            const int xmax4 = ((WW - ilw_al) >> 2) - 1;          // last in-row float4
            const float4* __restrict__ vsrc4 =
                reinterpret_cast<const float4*>(v);
            for (int j = tid; j < nj; j += TPB) {
                const int row = j / 12;                          // const-divisor magic
                const int x4  = j - row * 12;
                const int z   = (int)(((unsigned)row * mwhn) >> 20);   // exact
                const int y   = row - z * whn;
                const int x4c = min(x4, xmax4);
                const float4 val = __ldg(vsrc4 +
                    (((ild + z) * HW + (ilh + y) * WW + ilw_al) >> 2) + x4c);
                *reinterpret_cast<float4*>(sm + z * SZ + y * WPS + 4 * x4) = val;
            }
        }
        __syncthreads();

        const float fdm = (float)(ihd - 1), fhm = (float)(ihh - 1), fwm = (float)(ihw - 1);
        const float ildf = (float)ild, ilhf = (float)ilh, ilwf = (float)ilw;
        const int base = ild * SZ + ilh * WPS + ilw_al;

        int oidx = b * VOX + bd * HW + (bh + hy) * WW + bw + wx;

        #pragma unroll
        for (int k = 0; k < VPT; k++) {
            const float pd = pd0 + (float)k;
            const float ld = fmaf(a00, pd, t1d) + cD;
            const float lh = fmaf(a10, pd, t1h) + cH;
            const float lw = fmaf(a20, pd, t1w) + cW;

            const float td = fminf(fmaxf(ld, 0.0f), mD);
            const float th = fminf(fmaxf(lh, 0.0f), mH);
            const float tw = fminf(fmaxf(lw, 0.0f), mW);

            const float f0d = fminf(fmaxf(floorf(td), ildf), fdm);
            const float f0h = fminf(fmaxf(floorf(th), ilhf), fhm);
            const float f0w = fminf(fmaxf(floorf(tw), ilwf), fwm);

            const float w0d = (f0d - td) + 1.0f;
            const float w0h = (f0h - th) + 1.0f;
            const float w0w = (f0w - tw) + 1.0f;

            // flat smem index via one exact fp32 fma chain (values < 2^24)
            const int a0 = (int)(fmaf(f0d, (float)SZ, fmaf(f0h, (float)WPS, f0w))) - base;
            const int a1 = a0 + WPS;
            const int a2 = a0 + SZ;
            const int a3 = a2 + WPS;

            const float v000 = sm[a0],     v001 = sm[a0 + 1];
            const float v010 = sm[a1],     v011 = sm[a1 + 1];
            const float v100 = sm[a2],     v101 = sm[a2 + 1];
            const float v110 = sm[a3],     v111 = sm[a3 + 1];

            const float e00 = fmaf(w0w, v000 - v001, v001);
            const float e01 = fmaf(w0w, v010 - v011, v011);
            const float e10 = fmaf(w0w, v100 - v101, v101);
            const float e11 = fmaf(w0w, v110 - v111, v111);
            const float e0  = fmaf(w0h, e00 - e01, e01);
            const float e1  = fmaf(w0h, e10 - e11, e11);

            out[oidx] = fmaf(w0d, e0 - e1, e1);
            oidx += HW;
        }
    } else {
        // ---- uniform fallback: direct global gather (reference semantics) ----
        int oidx = b * VOX + bd * HW + (bh + hy) * WW + bw + wx;
        #pragma unroll
        for (int k = 0; k < VPT; k++) {
            const float pd = pd0 + (float)k;
            const float ld = fmaf(a00, pd, t1d) + cD;
            const float lh = fmaf(a10, pd, t1h) + cH;
            const float lw = fmaf(a20, pd, t1w) + cW;

            const float td = fminf(fmaxf(ld, 0.0f), mD);
            const float th = fminf(fmaxf(lh, 0.0f), mH);
            const float tw = fminf(fmaxf(lw, 0.0f), mW);

            const float f0d = fminf(floorf(td), mD - 1.0f);
            const float f0h = fminf(floorf(th), mH - 1.0f);
            const float f0w = fminf(floorf(tw), mW - 1.0f);

            const float w0d = (f0d - td) + 1.0f;
            const float w0h = (f0h - th) + 1.0f;
            const float w0w = (f0w - tw) + 1.0f;

            const int c00 = (int)f0d * HW + (int)f0h * WW + (int)f0w;
            const int c01 = c00 + WW;
            const int c10 = c00 + HW;
            const int c11 = c10 + WW;

            const float v000 = __ldg(v + c00), v001 = __ldg(v + c00 + 1);
            const float v010 = __ldg(v + c01), v011 = __ldg(v + c01 + 1);
            const float v100 = __ldg(v + c10), v101 = __ldg(v + c10 + 1);
            const float v110 = __ldg(v + c11), v111 = __ldg(v + c11 + 1);

            const float e00 = fmaf(w0w, v000 - v001, v001);
            const float e01 = fmaf(w0w, v010 - v011, v011);
            const float e10 = fmaf(w0w, v100 - v101, v101);
            const float e11 = fmaf(w0w, v110 - v111, v111);
            const float e0  = fmaf(w0h, e00 - e01, e01);
            const float e1  = fmaf(w0h, e10 - e11, e11);

            out[oidx] = fmaf(w0d, e0 - e1, e1);
            oidx += HW;
        }
    }
}

extern "C" void kernel_launch(void* const* d_in, const int* in_sizes, int n_in,
                              void* d_out, int out_size) {
    const float* vol = (const float*)d_in[0];
    const float* trf = (const float*)d_in[1];
    float* out = (float*)d_out;
    const int blocks = BATCH * (DD / TD) * (HH / TH) * (WW / TW);   // 9600
    st_affine_trilinear_v10<<<blocks, TPB>>>(vol, trf, out);
}